// round 7
// baseline (speedup 1.0000x reference)
#include <cuda_runtime.h>

// SSD MultiBox loss. B=128, A=8732, C=21.
// Inputs identified at runtime BY ELEMENT COUNT (ordering-proof):
//   B*A*C  -> classifi_output f32
//   B*A    -> classifi_label  int32 (jax x64-disabled downcasts int64->int32)
//   B*A*4  -> the two location arrays (SmoothL1 is symmetric; order irrelevant)
// Output: scalar f32.

#define NB 128
#define NA 8732
#define NC 21
#define TPB 256
#define BPR 35   // ceil(NA / TPB)

// Scratch (every slot read is overwritten first each launch; no zeroing needed).
__device__ float g_part[NB][BPR][4];   // per-block partials: loc, csum, cpos, pos
__device__ float g_row[NB];            // per-row total/denom
__device__ float g_con[NB * NA];       // fallback-only scratch
__device__ float g_cneg[NB * NA];      // fallback-only scratch

__device__ __forceinline__ float warpSum(float v) {
#pragma unroll
    for (int o = 16; o; o >>= 1) v += __shfl_xor_sync(0xffffffffu, v, o);
    return v;
}

// Per-anchor cross entropy: logsumexp(x) - x[label]. 21 logits in registers;
// label logit via unrolled predicated select (no dynamic register indexing).
__device__ __forceinline__ float compute_con(const float* __restrict__ cls, int labi) {
    float x[NC];
    float mx = -1e30f;
#pragma unroll
    for (int c = 0; c < NC; c++) { x[c] = __ldg(cls + c); mx = fmaxf(mx, x[c]); }
    float s = 0.f;
#pragma unroll
    for (int c = 0; c < NC; c++) s += __expf(x[c] - mx);
    float xl = x[0];
#pragma unroll
    for (int c = 1; c < NC; c++) if (labi == c) xl = x[c];
    return __logf(s) + mx - xl;
}

__global__ void k_main(const float* __restrict__ loc_out,
                       const float* __restrict__ cls_out,
                       const float* __restrict__ loc_lab,
                       const int* __restrict__ cls_lab) {
    const int b = blockIdx.y;
    const int a = blockIdx.x * TPB + threadIdx.x;

    float loc = 0.f, csum = 0.f, cpos = 0.f, pos = 0.f;
    if (a < NA) {
        const size_t ba = (size_t)b * NA + a;
        const int lab = cls_lab[ba];
        const float con = compute_con(cls_out + ba * (size_t)NC, lab);
        csum = con;
        if (lab > 0) {
            const float4 lo = *(const float4*)(loc_out + ba * 4);
            const float4 ll = *(const float4*)(loc_lab + ba * 4);
            float sl1 = 0.f, d, ad;
            d = lo.x - ll.x; ad = fabsf(d); sl1 += (ad < 1.f) ? 0.5f * d * d : ad - 0.5f;
            d = lo.y - ll.y; ad = fabsf(d); sl1 += (ad < 1.f) ? 0.5f * d * d : ad - 0.5f;
            d = lo.z - ll.z; ad = fabsf(d); sl1 += (ad < 1.f) ? 0.5f * d * d : ad - 0.5f;
            d = lo.w - ll.w; ad = fabsf(d); sl1 += (ad < 1.f) ? 0.5f * d * d : ad - 0.5f;
            loc = sl1; cpos = con; pos = 1.f;
        }
    }

    __shared__ float sm[TPB / 32][4];
    const int lane = threadIdx.x & 31, w = threadIdx.x >> 5;
    loc = warpSum(loc); csum = warpSum(csum); cpos = warpSum(cpos); pos = warpSum(pos);
    if (lane == 0) { sm[w][0] = loc; sm[w][1] = csum; sm[w][2] = cpos; sm[w][3] = pos; }
    __syncthreads();
    if (threadIdx.x < 4) {
        float s = 0.f;
#pragma unroll
        for (int i = 0; i < TPB / 32; i++) s += sm[i][threadIdx.x];
        g_part[b][blockIdx.x][threadIdx.x] = s;
    }
}

__global__ void k_row(const float* __restrict__ cls_out,
                      const int* __restrict__ cls_lab) {
    const int b = blockIdx.x;
    __shared__ float sm[TPB / 32][4];
    __shared__ float vals[4];

    float v0 = 0.f, v1 = 0.f, v2 = 0.f, v3 = 0.f;
    if (threadIdx.x < BPR) {
        v0 = g_part[b][threadIdx.x][0];
        v1 = g_part[b][threadIdx.x][1];
        v2 = g_part[b][threadIdx.x][2];
        v3 = g_part[b][threadIdx.x][3];
    }
    const int lane = threadIdx.x & 31, w = threadIdx.x >> 5;
    v0 = warpSum(v0); v1 = warpSum(v1); v2 = warpSum(v2); v3 = warpSum(v3);
    if (lane == 0) { sm[w][0] = v0; sm[w][1] = v1; sm[w][2] = v2; sm[w][3] = v3; }
    __syncthreads();
    if (threadIdx.x == 0) {
        float a0 = 0.f, a1 = 0.f, a2 = 0.f, a3 = 0.f;
#pragma unroll
        for (int i = 0; i < TPB / 32; i++) { a0 += sm[i][0]; a1 += sm[i][1]; a2 += sm[i][2]; a3 += sm[i][3]; }
        vals[0] = a0; vals[1] = a1; vals[2] = a2; vals[3] = a3;
    }
    __syncthreads();

    const float loc = vals[0], csum = vals[1], cpos = vals[2];
    const int p = (int)(vals[3] + 0.5f);
    int negn = min(3 * p, NA);
    if (negn == 0) negn = 3;

    if (negn >= NA) {
        // neg_mask all-true: con_loss = sum(con) + sum(con*mask).
        if (threadIdx.x == 0) {
            const float total = loc + csum + cpos;
            const float denom = (p != 0) ? (float)p : 1.f;
            g_row[b] = total / denom;
        }
        return;
    }

    // ---- Exact general fallback (never triggers for randint(0,21) labels) ----
    // Stable descending rank of con_neg: anchor i selected iff
    //   #{j: cn[j] > cn[i]} + #{j<i: cn[j]==cn[i]} < negn
    for (int a = threadIdx.x; a < NA; a += TPB) {
        const size_t ba = (size_t)b * NA + a;
        const int lab = cls_lab[ba];
        const float con = compute_con(cls_out + ba * (size_t)NC, lab);
        g_con[ba] = con;
        g_cneg[ba] = (lab > 0) ? 0.f : con;
    }
    __syncthreads();

    float acc = 0.f;
    for (int a = threadIdx.x; a < NA; a += TPB) {
        const size_t ba = (size_t)b * NA + a;
        const int lab = cls_lab[ba];
        const float con = g_con[ba];
        const float cn = g_cneg[ba];
        int cnt = 0;
        const float* cnrow = g_cneg + (size_t)b * NA;
        for (int j = 0; j < NA; j++) {
            const float cj = cnrow[j];
            cnt += (cj > cn) || (cj == cn && j < a);
        }
        const float sel = (cnt < negn) ? 1.f : 0.f;
        acc += con * (((lab > 0) ? 1.f : 0.f) + sel);
    }
    acc = warpSum(acc);
    if (lane == 0) sm[w][0] = acc;
    __syncthreads();
    if (threadIdx.x == 0) {
        float s = 0.f;
#pragma unroll
        for (int i = 0; i < TPB / 32; i++) s += sm[i][0];
        const float denom = (p != 0) ? (float)p : 1.f;
        g_row[b] = (loc + s) / denom;
    }
}

__global__ void k_final(float* __restrict__ out) {
    float v = (threadIdx.x < NB) ? g_row[threadIdx.x] : 0.f;
    v = warpSum(v);
    __shared__ float sm[4];
    const int lane = threadIdx.x & 31, w = threadIdx.x >> 5;
    if (lane == 0) sm[w] = v;
    __syncthreads();
    if (threadIdx.x == 0) {
        out[0] = (sm[0] + sm[1] + sm[2] + sm[3]) / (float)NB;
    }
}

extern "C" void kernel_launch(void* const* d_in, const int* in_sizes, int n_in,
                              void* d_out, int out_size) {
    (void)out_size;
    // Identify inputs by element count (ordering-proof).
    const float* cls_out = 0;
    const int*   cls_lab = 0;
    const float* loc_a = 0;
    const float* loc_b = 0;
    for (int i = 0; i < n_in; i++) {
        const long long n = in_sizes[i];
        if (n == (long long)NB * NA * NC)      cls_out = (const float*)d_in[i];
        else if (n == (long long)NB * NA)      cls_lab = (const int*)d_in[i];
        else if (n == (long long)NB * NA * 4) {
            if (!loc_a) loc_a = (const float*)d_in[i];
            else        loc_b = (const float*)d_in[i];
        }
    }

    dim3 grid(BPR, NB);
    k_main<<<grid, TPB>>>(loc_a, cls_out, loc_b, cls_lab);
    k_row<<<NB, TPB>>>(cls_out, cls_lab);
    k_final<<<1, 128>>>((float*)d_out);
}